// round 15
// baseline (speedup 1.0000x reference)
#include <cuda_runtime.h>
#include <math.h>
#include <stdint.h>

// ---------------------------------------------------------------------------
// GDER: out[b] = mean( Rx^2 + Ry^2 ) over valid 498x498 map.
// sum(Gy) is cancellation noise => Gy/sum(Gy) taps ~1e15 and Ry^2 dominates by
// >1e16 relative. Only the Gy path is computed, as a separable conv
// Gy = A(y)*B(x), 1/sum(Gy) folded into vertical taps. sum(Gy) replicated on
// host in numpy's exact f64 pairwise order (validated R1-R14, rel_err ~9e-8).
//
// R15 = R11 (best, 34.1us) + minimal-register prefetch:
//  - quads v0,v1 (window f0..f7) double-buffered by iteration parity, loaded
//    ONE ITERATION EARLY (gap ~400cyc > warm-L2 262cyc) — removes the HORIZ
//    head stall seen as issue=43%.
//  - quads v2..v4 single-buffered, issued before VERT (gap 130-230cyc).
//  - +8 regs vs R11; __launch_bounds__(128,4) keeps 4 blocks/SM (16 warps).
// ---------------------------------------------------------------------------

#define NB        64
#define W         512
#define OUTW      498
#define TILE      56
#define TILES_Y   9        // 9*56 = 504 >= 498

typedef unsigned long long u64;

struct Weights {
    float hw[8];   // horizontal symmetric taps: hw[0..6] pair weights, hw[7] center
    float vw[7];   // vertical antisymmetric taps (scaled by 1/sum(Gy))
};

__device__ double g_partials[NB * TILES_Y];
__device__ int    g_count[NB];   // zero-initialized; self-resetting

// ---- f32x2 packed helpers (sm_100+) ----
__device__ __forceinline__ u64 pack2(float lo, float hi) {
    u64 r; asm("mov.b64 %0, {%1, %2};" : "=l"(r) : "f"(lo), "f"(hi)); return r;
}
__device__ __forceinline__ void unpack2(u64 v, float& lo, float& hi) {
    asm("mov.b64 {%0, %1}, %2;" : "=f"(lo), "=f"(hi) : "l"(v));
}
__device__ __forceinline__ u64 fma2(u64 a, u64 b, u64 c) {
    u64 d; asm("fma.rn.f32x2 %0, %1, %2, %3;" : "=l"(d) : "l"(a), "l"(b), "l"(c)); return d;
}
__device__ __forceinline__ u64 add2(u64 a, u64 b) {
    u64 d; asm("add.rn.f32x2 %0, %1, %2;" : "=l"(d) : "l"(a), "l"(b)); return d;
}
__device__ __forceinline__ u64 neg2(u64 a) { return a ^ 0x8000000080000000ull; }

__global__ __launch_bounds__(128, 4) void gder_kernel(const float* __restrict__ x,
                                                      Weights wt,
                                                      float* __restrict__ out)
{
    const int t     = threadIdx.x;
    const int tileY = blockIdx.x;
    const int batch = blockIdx.y;
    const int y0    = tileY * TILE;
    const float* __restrict__ img = x + (size_t)batch * W * W;

    __shared__ double red[128];

    // packed weights
    u64 hw2[8], vp[7];
    #pragma unroll
    for (int j = 0; j < 8; ++j) hw2[j] = pack2(wt.hw[j], wt.hw[j]);
    #pragma unroll
    for (int k = 0; k < 7; ++k) vp[k] = pack2(wt.vw[k], wt.vw[k]);
    #define HWM(j) (hw2[(j) < 8 ? (j) : 14 - (j)])

    const int c = 4 * t;   // this thread's 4 output columns c..c+3

    // Edge handling at init only (validated R10-R11):
    //  t <= 123: cb = c, 5 quads.  t == 124: cb = 496, 4 quads, f16..19 = 0
    //  (feeds only masked outputs). t >= 125: cb = 492, outputs fully masked.
    const int  cb  = (c <= 496) ? c : 492;
    const bool do5 = (c != 496);

    // output validity masks (packed pairs A=(c,c+1), B=(c+2,c+3))
    const u64 LOm = 0x00000000FFFFFFFFull, HIm = 0xFFFFFFFF00000000ull;
    const u64 mA = (c     <= 497 ? LOm : 0ull) | (c + 1 <= 497 ? HIm : 0ull);
    const u64 mB = (c + 2 <= 497 ? LOm : 0ull) | (c + 3 <= 497 ? HIm : 0ull);

    // walking row pointer: immediate-offset LDG.128s, +W per row
    const float* p = img + (size_t)y0 * W + cb;

    // prefetch buffers: window f0..f7 (quads v0,v1), parity double-buffered
    union Quad2 { float f[8]; u64 d[4]; float4 v[2]; };
    // singles: window f8..f19 (quads v2,v3,v4); sg.f[i] = window f[i+8]
    union Quad3 { float f[12]; u64 d[6]; float4 v[3]; };
    Quad2 pf0, pf1;
    Quad3 sg;
    sg.f[8] = 0.f; sg.f[9] = 0.f; sg.f[10] = 0.f; sg.f[11] = 0.f;  // f16..f19

    #define LOAD_PF(P) do {                                     \
        (P).v[0] = *reinterpret_cast<const float4*>(p);         \
        (P).v[1] = *reinterpret_cast<const float4*>(p + 4);     \
    } while (0)
    #define LOAD_SG() do {                                      \
        sg.v[0] = *reinterpret_cast<const float4*>(p + 8);      \
        sg.v[1] = *reinterpret_cast<const float4*>(p + 12);     \
        if (do5) sg.v[2] = *reinterpret_cast<const float4*>(p + 16); \
    } while (0)

    // window pair u_j = (f[j], f[j+1]); j compile-time under full unroll.
    // even pairs are aligned load register pairs (free f32x2 operands).
    #define UPAIR2(P, j)                                                       \
        ((j) == 7 ? pack2((P).f[7], sg.f[0])                                   \
         : ((j) < 7  ? (((j) & 1) ? pack2((P).f[j], (P).f[(j) + 1])            \
                                  : (P).d[(j) / 2])                            \
                     : (((j) & 1) ? pack2(sg.f[(j) - 8], sg.f[(j) - 7])        \
                                  : sg.d[((j) - 8) / 2])))

    // horizontal: split 8/7 chains, pairs A=(f window offset 0), B=(offset 2)
    #define HORIZ2(P, dA, dB) do {                                             \
        u64 a0 = 0ull, a1 = 0ull, b0 = 0ull, b1 = 0ull;                        \
        _Pragma("unroll")                                                      \
        for (int j = 0; j < 15; ++j) {                                         \
            const u64 u = UPAIR2(P, j);                                        \
            if (j <= 7) a0 = fma2(HWM(j), u, a0);                              \
            else        a1 = fma2(HWM(j), u, a1);                              \
        }                                                                      \
        _Pragma("unroll")                                                      \
        for (int j = 0; j < 15; ++j) {                                         \
            const u64 u = UPAIR2(P, j + 2);                                    \
            if (j <= 7) b0 = fma2(HWM(j), u, b0);                              \
            else        b1 = fma2(HWM(j), u, b1);                              \
        }                                                                      \
        dA = add2(a0, a1);                                                     \
        dB = add2(b0, b1);                                                     \
    } while (0)

    // vertical: ring slot q = oldest row; accumulate masked squares
    #define VERTQ(q) do {                                                      \
        u64 aA = 0ull, bAc = 0ull, aB = 0ull, bBc = 0ull;                      \
        _Pragma("unroll")                                                      \
        for (int k = 0; k < 7; ++k) {                                          \
            aA  = fma2(vp[k], rA[((q) + k) % 15], aA);                         \
            bAc = fma2(vp[k], rA[((q) + 14 - k) % 15], bAc);                   \
            aB  = fma2(vp[k], rB[((q) + k) % 15], aB);                         \
            bBc = fma2(vp[k], rB[((q) + 14 - k) % 15], bBc);                   \
        }                                                                      \
        u64 oA = add2(aA, neg2(bAc));                                          \
        u64 oB = add2(aB, neg2(bBc));                                          \
        if (t >= 124) { oA &= mA; oB &= mB; }                                  \
        facc = fma2(oA, oA, facc);                                             \
        facc = fma2(oB, oB, facc);                                             \
    } while (0)

    // ring: slot j holds row y0+j (mod 15)
    u64 rA[15], rB[15];

    // init rows y0..y0+14 (always valid: y0+14 <= 462); pf0 used as scratch
    #pragma unroll
    for (int j = 0; j < 15; ++j) {
        LOAD_PF(pf0);
        LOAD_SG();
        HORIZ2(pf0, rA[j], rB[j]);
        p += W;
    }

    u64 facc = 0ull;

    // prime the pipeline: v0,v1 of row y0+15 (consumed at i=0, parity 0)
    LOAD_PF(pf0);

    // fast iterations i = 0..44 (i = 15g+q): provably in-bounds for EVERY
    // tile (SG row y0+15+i <= 507; PF row y0+16+i <= 508; outputs <= 492).
    //   LOAD_SG  row y0+15+i  (consumed this iter, after VERT)
    //   LOAD_PF  row y0+16+i  (consumed NEXT iter — full-iteration gap)
    //   VERT     output y0+i
    //   HORIZ    row y0+15+i -> ring slot i%15
    #pragma unroll
    for (int g = 0; g < 3; ++g) {
        #pragma unroll
        for (int q = 0; q < 15; ++q) {
            const int i = g * 15 + q;
            LOAD_SG();
            p += W;
            if ((i & 1) == 0) { LOAD_PF(pf1); } else { LOAD_PF(pf0); }
            VERTQ(q);
            if ((i & 1) == 0) { HORIZ2(pf0, rA[q], rB[q]); }
            else              { HORIZ2(pf1, rA[q], rB[q]); }
        }
    }

    // epilogue i = 45..55 (guards bind only for tile 8, y0 = 448):
    //  dl  = row y0+15+i < 512 (SG load + HORIZ insert; pf for this row was
    //        guarded by the same condition last iteration)
    //  dpf = row y0+16+i < 512
    //  dv  = output y0+i < 498
    #pragma unroll
    for (int e = 0; e < 11; ++e) {
        const int i = 45 + e;
        const int q = i % 15;
        const bool dl  = (y0 + 15 + i < W);
        const bool dpf = (y0 + 16 + i < W);
        const bool dv  = (y0 + i < OUTW);
        if (dl) LOAD_SG();
        p += W;
        if (dpf) { if ((i & 1) == 0) { LOAD_PF(pf1); } else { LOAD_PF(pf0); } }
        if (dv) VERTQ(q);
        if (dl) {
            if ((i & 1) == 0) { HORIZ2(pf0, rA[q], rB[q]); }
            else              { HORIZ2(pf1, rA[q], rB[q]); }
        }
    }

    // deterministic block reduction in double
    {
        float flo, fhi;
        unpack2(facc, flo, fhi);
        red[t] = (double)flo + (double)fhi;
    }
    __syncthreads();
    #pragma unroll
    for (int s = 64; s > 0; s >>= 1) {
        if (t < s) red[t] += red[t + s];
        __syncthreads();
    }
    if (t == 0) {
        g_partials[batch * TILES_Y + tileY] = red[0];
        __threadfence();
        const int old = atomicAdd(&g_count[batch], 1);
        if (old == TILES_Y - 1) {   // last block for this batch: fixed-order sum
            __threadfence();
            double s = 0.0;
            #pragma unroll
            for (int i = 0; i < TILES_Y; ++i)
                s += __ldcg(&g_partials[batch * TILES_Y + i]);
            out[batch] = (float)(s * (1.0 / ((double)OUTW * (double)OUTW)));
            g_count[batch] = 0;     // reset for next graph replay
        }
    }
}

// ---------------------------------------------------------------------------
// Host side: replicate numpy float64 semantics exactly (validated R1-R14).
// ---------------------------------------------------------------------------

// numpy's pairwise_sum for contiguous float64 (PW_BLOCKSIZE = 128)
static double np_pairwise(const double* a, int n)
{
    if (n < 8) {
        double res = 0.0;
        for (int i = 0; i < n; ++i) res += a[i];
        return res;
    }
    else if (n <= 128) {
        double r[8];
        for (int j = 0; j < 8; ++j) r[j] = a[j];
        int i;
        for (i = 8; i < n - (n % 8); i += 8)
            for (int j = 0; j < 8; ++j) r[j] += a[i + j];
        double res = ((r[0] + r[1]) + (r[2] + r[3])) + ((r[4] + r[5]) + (r[6] + r[7]));
        for (; i < n; ++i) res += a[i];
        return res;
    }
    else {
        int n2 = n / 2;
        n2 -= n2 % 8;
        return np_pairwise(a, n2) + np_pairwise(a + n2, n - n2);
    }
}

extern "C" void kernel_launch(void* const* d_in, const int* in_sizes, int n_in,
                              void* d_out, int out_size)
{
    (void)in_sizes; (void)n_in; (void)out_size;
    const float* x  = (const float*)d_in[0];
    float*      out = (float*)d_out;

    const double sig     = 7.0 / 2.5;              // N=15//2=7; sig = N/2.5
    const double sig2    = pow(sig, 2.0);          // sig ** 2 (CPython float_pow -> libm pow)
    const double twosig2 = 2.0 * sig2;
    const double denomG  = (2.0 * M_PI) * sig;

    double Gy[225];
    for (int i = 0; i < 15; ++i) {
        const int yy = i - 7;
        for (int j = 0; j < 15; ++j) {
            const int xx = j - 7;
            const double G = exp((double)(-(xx * xx + yy * yy)) / twosig2) / denomG;
            Gy[i * 15 + j] = ((double)(-yy) * G) / sig2;
        }
    }
    const double s = np_pairwise(Gy, 225);         // np.sum(Gy), numpy pairwise order

    Weights wt;
    for (int j = 0; j < 8; ++j) {
        const int xx = j - 7;
        wt.hw[j] = (float)(exp((double)(-(xx * xx)) / twosig2) / denomG);
    }
    for (int k = 0; k < 7; ++k) {
        const int yy = k - 7;
        const double A = (((double)(-yy) * exp((double)(-(yy * yy)) / twosig2)) / sig2) / s;
        wt.vw[k] = (float)A;
    }

    dim3 grid(TILES_Y, NB);
    gder_kernel<<<grid, 128>>>(x, wt, out);
}

// round 16
// speedup vs baseline: 1.1154x; 1.1154x over previous
#include <cuda_runtime.h>
#include <math.h>
#include <stdint.h>

// ---------------------------------------------------------------------------
// GDER: out[b] = mean( Rx^2 + Ry^2 ) over valid 498x498 map.
// sum(Gy) is cancellation noise => Gy/sum(Gy) taps ~1e15 and Ry^2 dominates by
// >1e16 relative. Only the Gy path is computed, as a separable conv
// Gy = A(y)*B(x), 1/sum(Gy) folded into vertical taps. sum(Gy) replicated on
// host in numpy's exact f64 pairwise order (validated R1-R15, rel_err ~9e-8).
//
// R16 = R11 (best, 34.1us) + REGISTER-FREE next-row L1 prefetch:
// one prefetch.global.L1 per row (thread addresses stride 16B -> one per
// thread covers all 128B lines of the warp span). Next-row consume latency
// drops ~250cyc (L2) -> ~39cyc (L1), matching the calibrated ~150cyc/row
// exposed stall that pins issue at 43%. Zero register cost; prefetches
// emitted only where provably in-bounds (init + fast loop).
// ---------------------------------------------------------------------------

#define NB        64
#define W         512
#define OUTW      498
#define TILE      56
#define TILES_Y   9        // 9*56 = 504 >= 498

typedef unsigned long long u64;

struct Weights {
    float hw[8];   // horizontal symmetric taps: hw[0..6] pair weights, hw[7] center
    float vw[7];   // vertical antisymmetric taps (scaled by 1/sum(Gy))
};

__device__ double g_partials[NB * TILES_Y];
__device__ int    g_count[NB];   // zero-initialized; self-resetting

// ---- f32x2 packed helpers (sm_100+) ----
__device__ __forceinline__ u64 pack2(float lo, float hi) {
    u64 r; asm("mov.b64 %0, {%1, %2};" : "=l"(r) : "f"(lo), "f"(hi)); return r;
}
__device__ __forceinline__ void unpack2(u64 v, float& lo, float& hi) {
    asm("mov.b64 {%0, %1}, %2;" : "=f"(lo), "=f"(hi) : "l"(v));
}
__device__ __forceinline__ u64 fma2(u64 a, u64 b, u64 c) {
    u64 d; asm("fma.rn.f32x2 %0, %1, %2, %3;" : "=l"(d) : "l"(a), "l"(b), "l"(c)); return d;
}
__device__ __forceinline__ u64 add2(u64 a, u64 b) {
    u64 d; asm("add.rn.f32x2 %0, %1, %2;" : "=l"(d) : "l"(a), "l"(b)); return d;
}
__device__ __forceinline__ u64 neg2(u64 a) { return a ^ 0x8000000080000000ull; }
__device__ __forceinline__ void prefetch_l1(const float* a) {
    asm volatile("prefetch.global.L1 [%0];" :: "l"(a));
}

__global__ __launch_bounds__(128, 4) void gder_kernel(const float* __restrict__ x,
                                                      Weights wt,
                                                      float* __restrict__ out)
{
    const int t     = threadIdx.x;
    const int tileY = blockIdx.x;
    const int batch = blockIdx.y;
    const int y0    = tileY * TILE;
    const float* __restrict__ img = x + (size_t)batch * W * W;

    __shared__ double red[128];

    // packed weights
    u64 hw2[8], vp[7];
    #pragma unroll
    for (int j = 0; j < 8; ++j) hw2[j] = pack2(wt.hw[j], wt.hw[j]);
    #pragma unroll
    for (int k = 0; k < 7; ++k) vp[k] = pack2(wt.vw[k], wt.vw[k]);
    #define HWM(j) (hw2[(j) < 8 ? (j) : 14 - (j)])

    const int c = 4 * t;   // this thread's 4 output columns c..c+3

    // Edge handling at init only (validated R10-R11):
    //  t <= 123: cb = c, 5 loads.   t == 124: cb = 496, 4 loads, f[16..19]=0
    //  (feeds only masked outputs). t >= 125: cb = 492, outputs fully masked.
    const int  cb  = (c <= 496) ? c : 492;
    const bool do5 = (c != 496);

    // output validity masks (packed pairs A=(c,c+1), B=(c+2,c+3))
    const u64 LOm = 0x00000000FFFFFFFFull, HIm = 0xFFFFFFFF00000000ull;
    const u64 mA = (c     <= 497 ? LOm : 0ull) | (c + 1 <= 497 ? HIm : 0ull);
    const u64 mB = (c + 2 <= 497 ? LOm : 0ull) | (c + 3 <= 497 ? HIm : 0ull);

    // walking row pointer: immediate-offset LDG.128s, +W per row
    const float* p = img + (size_t)y0 * W + cb;

    // window buffer: union so even pairs (f[2m], f[2m+1]) are load register
    // pairs (valid f32x2 operands); odd pairs via pack2
    union InBuf { float f[20]; u64 d[10]; float4 v[5]; };
    InBuf in;
    in.f[16] = 0.f; in.f[17] = 0.f; in.f[18] = 0.f; in.f[19] = 0.f;

    #define LOAD_ROW() do {                                          \
        in.v[0] = *reinterpret_cast<const float4*>(p);               \
        in.v[1] = *reinterpret_cast<const float4*>(p + 4);           \
        in.v[2] = *reinterpret_cast<const float4*>(p + 8);           \
        in.v[3] = *reinterpret_cast<const float4*>(p + 12);          \
        if (do5) in.v[4] = *reinterpret_cast<const float4*>(p + 16); \
    } while (0)

    #define UPAIR(j) (((j) & 1) ? pack2(in.f[j], in.f[(j) + 1]) : in.d[(j) / 2])

    #define HORIZ(hA, hB) do {                                       \
        u64 hA0 = 0ull, hA1 = 0ull, hB0 = 0ull, hB1 = 0ull;          \
        _Pragma("unroll")                                            \
        for (int j = 0; j < 15; ++j) {                               \
            const u64 uj = UPAIR(j);                                 \
            if (j <= 7) hA0 = fma2(HWM(j), uj, hA0);                 \
            else        hA1 = fma2(HWM(j), uj, hA1);                 \
        }                                                            \
        _Pragma("unroll")                                            \
        for (int j = 0; j < 15; ++j) {                               \
            const u64 uj = UPAIR(j + 2);                             \
            if (j <= 7) hB0 = fma2(HWM(j), uj, hB0);                 \
            else        hB1 = fma2(HWM(j), uj, hB1);                 \
        }                                                            \
        hA = add2(hA0, hA1);                                         \
        hB = add2(hB0, hB1);                                         \
    } while (0)

    // vertical for the output whose oldest ring row sits in slot q
    #define VERT(q) do {                                                        \
        u64 aA = 0ull, bA = 0ull, aB = 0ull, bB = 0ull;                         \
        _Pragma("unroll")                                                       \
        for (int k = 0; k < 7; ++k) {                                           \
            aA = fma2(vp[k], rA[((q) + k) % 15], aA);                           \
            bA = fma2(vp[k], rA[((q) + 14 - k) % 15], bA);                      \
            aB = fma2(vp[k], rB[((q) + k) % 15], aB);                           \
            bB = fma2(vp[k], rB[((q) + 14 - k) % 15], bB);                      \
        }                                                                       \
        u64 oA = add2(aA, neg2(bA));                                            \
        u64 oB = add2(aB, neg2(bB));                                            \
        if (t >= 124) { oA &= mA; oB &= mB; }                                   \
        fA = fma2(oA, oA, fA);                                                  \
        fB = fma2(oB, oB, fB);                                                  \
    } while (0)

    // ring of horizontal results: 15 rows x 2 packed pairs
    u64 rA[15], rB[15];

    // init rows y0..y0+13 (always valid); prefetch next row (<= y0+14 <= 462)
    #pragma unroll
    for (int j = 0; j < 14; ++j) {
        LOAD_ROW();
        p += W;
        prefetch_l1(p);                    // next row, always in-bounds
        HORIZ(rA[j], rB[j]);
    }
    // peel i=0: row y0+14 -> slot 14 (always valid: y0+14 <= 462)
    LOAD_ROW();
    p += W;
    prefetch_l1(p);                        // row y0+15 <= 463, in-bounds
    HORIZ(rA[14], rB[14]);

    u64 fA = 0ull, fB = 0ull;

    // fast iterations i = 1..45 (3 x 15): in-bounds for EVERY tile
    // (loads rows <= y0+59 <= 507 < 512; prefetch rows <= y0+60 <= 508;
    //  outputs <= y0+44 <= 492 < 498).
    // Iter (g,q): load row y0+15+15g+q; prefetch the row after; VERT output
    // row y0+15g+q; insert into slot q (just consumed as oldest).
    #pragma unroll
    for (int g = 0; g < 3; ++g) {
        #pragma unroll
        for (int q = 0; q < 15; ++q) {
            LOAD_ROW();
            p += W;
            prefetch_l1(p);                // next row, provably in-bounds
            VERT(q);                       // output row y0 + 15g + q
            HORIZ(rA[q], rB[q]);           // insert row y0+15+15g+q
        }
    }

    // epilogue: i = 46..56 (11 rows), guards bind only for tile 8 (y0=448):
    // loads rows y0+60+q vs 512; outputs y0+45+q vs 498. No prefetch here.
    #pragma unroll
    for (int q = 0; q < 11; ++q) {
        const bool doLoad = (y0 + 60 + q < W);
        const bool doVert = (y0 + 45 + q < OUTW);
        if (doLoad) LOAD_ROW();
        p += W;
        if (doVert) VERT(q);               // output row y0 + 45 + q
        if (doLoad) HORIZ(rA[q], rB[q]);   // insert row y0 + 60 + q
    }

    // deterministic block reduction in double
    {
        const u64 facc = add2(fA, fB);
        float flo, fhi;
        unpack2(facc, flo, fhi);
        red[t] = (double)flo + (double)fhi;
    }
    __syncthreads();
    #pragma unroll
    for (int s = 64; s > 0; s >>= 1) {
        if (t < s) red[t] += red[t + s];
        __syncthreads();
    }
    if (t == 0) {
        g_partials[batch * TILES_Y + tileY] = red[0];
        __threadfence();
        const int old = atomicAdd(&g_count[batch], 1);
        if (old == TILES_Y - 1) {   // last block for this batch: fixed-order sum
            __threadfence();
            double s = 0.0;
            #pragma unroll
            for (int i = 0; i < TILES_Y; ++i)
                s += __ldcg(&g_partials[batch * TILES_Y + i]);
            out[batch] = (float)(s * (1.0 / ((double)OUTW * (double)OUTW)));
            g_count[batch] = 0;     // reset for next graph replay
        }
    }
}

// ---------------------------------------------------------------------------
// Host side: replicate numpy float64 semantics exactly (validated R1-R15).
// ---------------------------------------------------------------------------

// numpy's pairwise_sum for contiguous float64 (PW_BLOCKSIZE = 128)
static double np_pairwise(const double* a, int n)
{
    if (n < 8) {
        double res = 0.0;
        for (int i = 0; i < n; ++i) res += a[i];
        return res;
    }
    else if (n <= 128) {
        double r[8];
        for (int j = 0; j < 8; ++j) r[j] = a[j];
        int i;
        for (i = 8; i < n - (n % 8); i += 8)
            for (int j = 0; j < 8; ++j) r[j] += a[i + j];
        double res = ((r[0] + r[1]) + (r[2] + r[3])) + ((r[4] + r[5]) + (r[6] + r[7]));
        for (; i < n; ++i) res += a[i];
        return res;
    }
    else {
        int n2 = n / 2;
        n2 -= n2 % 8;
        return np_pairwise(a, n2) + np_pairwise(a + n2, n - n2);
    }
}

extern "C" void kernel_launch(void* const* d_in, const int* in_sizes, int n_in,
                              void* d_out, int out_size)
{
    (void)in_sizes; (void)n_in; (void)out_size;
    const float* x  = (const float*)d_in[0];
    float*      out = (float*)d_out;

    const double sig     = 7.0 / 2.5;              // N=15//2=7; sig = N/2.5
    const double sig2    = pow(sig, 2.0);          // sig ** 2 (CPython float_pow -> libm pow)
    const double twosig2 = 2.0 * sig2;
    const double denomG  = (2.0 * M_PI) * sig;

    double Gy[225];
    for (int i = 0; i < 15; ++i) {
        const int yy = i - 7;
        for (int j = 0; j < 15; ++j) {
            const int xx = j - 7;
            const double G = exp((double)(-(xx * xx + yy * yy)) / twosig2) / denomG;
            Gy[i * 15 + j] = ((double)(-yy) * G) / sig2;
        }
    }
    const double s = np_pairwise(Gy, 225);         // np.sum(Gy), numpy pairwise order

    Weights wt;
    for (int j = 0; j < 8; ++j) {
        const int xx = j - 7;
        wt.hw[j] = (float)(exp((double)(-(xx * xx)) / twosig2) / denomG);
    }
    for (int k = 0; k < 7; ++k) {
        const int yy = k - 7;
        const double A = (((double)(-yy) * exp((double)(-(yy * yy)) / twosig2)) / sig2) / s;
        wt.vw[k] = (float)A;
    }

    dim3 grid(TILES_Y, NB);
    gder_kernel<<<grid, 128>>>(x, wt, out);
}